// round 6
// baseline (speedup 1.0000x reference)
#include <cuda_runtime.h>
#include <cuda_bf16.h>

// Problem constants
#define T_STEPS 256
#define B_SZ    128
#define F_SZ    2500
#define H_SZ    128
#define O_SZ    2

// Scratch (allocation-free rule: __device__ globals)
__device__ float  g_cur1[T_STEPS * B_SZ * H_SZ];   // [t][b][h]
__device__ float  g_spk1[T_STEPS * B_SZ * H_SZ];   // [t][b][h]
__device__ double g_cur2[T_STEPS * B_SZ * O_SZ];   // [t][b][o]

// ---------------------------------------------------------------------------
// Kernel 1: cur1[t,b,h] = sum_f x[b,t,f] * W1[h,f] + b1[h]
// grid = (2, T): blockIdx.x = 64-row b tile, blockIdx.y = t.
// Tile BM=64(b) x BN=128(h), BK=16, 4x8 per thread, 256 threads.
// Two-level compensated accumulation: fp32 chunk accumulator (error ~1e-8),
// Kahan-merged into running accumulator -> total dot error ~1e-7 std.
// ---------------------------------------------------------------------------
__global__ void __launch_bounds__(256, 2) gemm1_kernel(
    const float* __restrict__ x,   // [B, T, F]
    const float* __restrict__ W1,  // [H, F]
    const float* __restrict__ b1)  // [H]
{
    const int bm  = blockIdx.x;   // 0..1 (b tile)
    const int t   = blockIdx.y;   // 0..255
    const int tid = threadIdx.x;

    __shared__ float Xs[16][68];   // [k][b], +4 pad
    __shared__ float Ws[16][132];  // [k][h], +4 pad

    float acc[4][8], comp[4][8], cacc[4][8];
    #pragma unroll
    for (int i = 0; i < 4; i++)
        #pragma unroll
        for (int j = 0; j < 8; j++) { acc[i][j] = 0.f; comp[i][j] = 0.f; }

    const int tr = tid >> 4;   // 0..15 -> b rows tr*4..+3
    const int tc = tid & 15;   // 0..15 -> h cols tc*8..+7

    for (int k0 = 0; k0 < F_SZ; k0 += 16) {
        // Load Xs: 64 rows x 16 k = 256 float4, one per thread.
        {
            const int r  = tid >> 2;          // 0..63 (b row in tile)
            const int kv = (tid & 3) << 2;    // 0,4,8,12
            const int f  = k0 + kv;
            float4 v = make_float4(0.f, 0.f, 0.f, 0.f);
            if (f < F_SZ)  // F_SZ % 4 == 0 -> float4 fully valid or fully OOB
                v = *reinterpret_cast<const float4*>(
                        &x[((bm * 64 + r) * T_STEPS + t) * F_SZ + f]);
            Xs[kv + 0][r] = v.x; Xs[kv + 1][r] = v.y;
            Xs[kv + 2][r] = v.z; Xs[kv + 3][r] = v.w;
        }
        // Load Ws: 128 rows x 16 k = 512 float4, two per thread.
        #pragma unroll
        for (int i = 0; i < 2; i++) {
            const int L  = tid + i * 256;
            const int r  = L >> 2;            // 0..127 (h row)
            const int kv = (L & 3) << 2;
            const int f  = k0 + kv;
            float4 v = make_float4(0.f, 0.f, 0.f, 0.f);
            if (f < F_SZ)
                v = *reinterpret_cast<const float4*>(&W1[r * F_SZ + f]);
            Ws[kv + 0][r] = v.x; Ws[kv + 1][r] = v.y;
            Ws[kv + 2][r] = v.z; Ws[kv + 3][r] = v.w;
        }
        __syncthreads();

        #pragma unroll
        for (int i = 0; i < 4; i++)
            #pragma unroll
            for (int j = 0; j < 8; j++) cacc[i][j] = 0.f;

        #pragma unroll
        for (int k = 0; k < 16; k++) {
            float a[4], b[8];
            *reinterpret_cast<float4*>(a)     = *reinterpret_cast<const float4*>(&Xs[k][tr * 4]);
            *reinterpret_cast<float4*>(b)     = *reinterpret_cast<const float4*>(&Ws[k][tc * 8]);
            *reinterpret_cast<float4*>(b + 4) = *reinterpret_cast<const float4*>(&Ws[k][tc * 8 + 4]);
            #pragma unroll
            for (int i = 0; i < 4; i++)
                #pragma unroll
                for (int j = 0; j < 8; j++)
                    cacc[i][j] = fmaf(a[i], b[j], cacc[i][j]);
        }

        // Kahan merge of chunk sum into running accumulator
        #pragma unroll
        for (int i = 0; i < 4; i++)
            #pragma unroll
            for (int j = 0; j < 8; j++) {
                float y   = cacc[i][j] - comp[i][j];
                float tmp = acc[i][j] + y;
                comp[i][j] = (tmp - acc[i][j]) - y;
                acc[i][j]  = tmp;
            }
        __syncthreads();
    }

    float bias[8];
    #pragma unroll
    for (int j = 0; j < 8; j++) bias[j] = b1[tc * 8 + j];

    #pragma unroll
    for (int i = 0; i < 4; i++) {
        const int brow = bm * 64 + tr * 4 + i;
        float* dst = &g_cur1[(t * B_SZ + brow) * H_SZ + tc * 8];
        float r[8];
        #pragma unroll
        for (int j = 0; j < 8; j++)
            r[j] = (acc[i][j] + comp[i][j]) + bias[j];
        *reinterpret_cast<float4*>(dst)     = *reinterpret_cast<float4*>(r);
        *reinterpret_cast<float4*>(dst + 4) = *reinterpret_cast<float4*>(r + 4);
    }
}

// ---------------------------------------------------------------------------
// Kernel 2: LIF layer 1 in fp64. One thread per (b,h) = 16384 threads.
// mem = beta*mem + cur - (mem_prev > 1); spk = (mem > 1).
// ---------------------------------------------------------------------------
__global__ void lif1_kernel()
{
    const int g = blockIdx.x * blockDim.x + threadIdx.x;  // b*H + h
    const double beta = (double)0.9f;  // match reference's fp32 constant
    double mem = 0.0;
    for (int t0 = 0; t0 < T_STEPS; t0 += 16) {
        float c[16];
        #pragma unroll
        for (int i = 0; i < 16; i++)
            c[i] = g_cur1[(t0 + i) * (B_SZ * H_SZ) + g];
        #pragma unroll
        for (int i = 0; i < 16; i++) {
            const double rst = (mem > 1.0) ? 1.0 : 0.0;
            mem = beta * mem + (double)c[i] - rst;
            g_spk1[(t0 + i) * (B_SZ * H_SZ) + g] = (mem > 1.0) ? 1.0f : 0.0f;
        }
    }
}

// ---------------------------------------------------------------------------
// Kernel 3: cur2[t,b,o] = sum_h spk1[t,b,h] * W2[o,h] + b2[o]  (fp64 exact:
// spk1 in {0,1} so products are exact fp32, summed in double).
// One warp per (t,b): 32768 warps.
// ---------------------------------------------------------------------------
__global__ void cur2_kernel(const float* __restrict__ W2, const float* __restrict__ b2)
{
    const int gw   = (blockIdx.x * blockDim.x + threadIdx.x) >> 5;  // t*B + b
    const int lane = threadIdx.x & 31;
    const float* row = g_spk1 + (size_t)gw * H_SZ;

    double s0 = 0.0, s1 = 0.0;
    #pragma unroll
    for (int j = 0; j < 4; j++) {
        const int h = lane + j * 32;
        const float v = row[h];
        s0 += (double)(v * W2[h]);
        s1 += (double)(v * W2[H_SZ + h]);
    }
    #pragma unroll
    for (int off = 16; off > 0; off >>= 1) {
        s0 += __shfl_xor_sync(0xffffffffu, s0, off);
        s1 += __shfl_xor_sync(0xffffffffu, s1, off);
    }
    if (lane == 0) {
        g_cur2[gw * 2 + 0] = s0 + (double)b2[0];
        g_cur2[gw * 2 + 1] = s1 + (double)b2[1];
    }
}

// ---------------------------------------------------------------------------
// Kernel 4: LIF layer 2 in fp64 + write outputs.
// One thread per (b,o) = 256 threads, single block.
// out = [spk_rec (T,B,O) | mem_rec (T,B,O)] flattened, fp32.
// ---------------------------------------------------------------------------
__global__ void lif2_kernel(float* __restrict__ out)
{
    const int g = threadIdx.x;  // b*O + o, 0..255
    float* out_spk = out;
    float* out_mem = out + T_STEPS * B_SZ * O_SZ;
    const double beta = (double)0.9f;

    double mem = 0.0;
    for (int t0 = 0; t0 < T_STEPS; t0 += 16) {
        double c[16];
        #pragma unroll
        for (int i = 0; i < 16; i++)
            c[i] = g_cur2[(t0 + i) * (B_SZ * O_SZ) + g];
        #pragma unroll
        for (int i = 0; i < 16; i++) {
            const double rst = (mem > 1.0) ? 1.0 : 0.0;
            mem = beta * mem + c[i] - rst;
            out_spk[(t0 + i) * (B_SZ * O_SZ) + g] = (mem > 1.0) ? 1.0f : 0.0f;
            out_mem[(t0 + i) * (B_SZ * O_SZ) + g] = (float)mem;
        }
    }
}

// ---------------------------------------------------------------------------
extern "C" void kernel_launch(void* const* d_in, const int* in_sizes, int n_in,
                              void* d_out, int out_size)
{
    const float* x  = (const float*)d_in[0];  // [B, T, F]
    const float* W1 = (const float*)d_in[1];  // [H, F]
    const float* b1 = (const float*)d_in[2];  // [H]
    const float* W2 = (const float*)d_in[3];  // [O, H]
    const float* b2 = (const float*)d_in[4];  // [O]
    float* out = (float*)d_out;

    dim3 g1(2, T_STEPS);
    gemm1_kernel<<<g1, 256>>>(x, W1, b1);                      // 512 CTAs
    lif1_kernel<<<(B_SZ * H_SZ) / 256, 256>>>();               // 64 CTAs
    cur2_kernel<<<(T_STEPS * B_SZ * 32) / 256, 256>>>(W2, b2); // 4096 CTAs
    lif2_kernel<<<1, 256>>>(out);                              // tiny sequential tail
}

// round 7
// speedup vs baseline: 1.1746x; 1.1746x over previous
#include <cuda_runtime.h>
#include <cuda_bf16.h>

// Problem constants
#define T_STEPS 256
#define B_SZ    128
#define F_SZ    2500
#define H_SZ    128
#define O_SZ    2

typedef unsigned long long u64;

// Scratch (allocation-free rule: __device__ globals)
__device__ float  g_cur1[T_STEPS * B_SZ * H_SZ];   // [t][b][h]
__device__ float  g_spk1[T_STEPS * B_SZ * H_SZ];   // [t][b][h]
__device__ double g_cur2[T_STEPS * B_SZ * O_SZ];   // [t][b][o]

// ---- packed f32x2 helpers (sm_103a; ptxas never auto-fuses these) ----------
__device__ __forceinline__ u64 pk2(float lo, float hi) {
    u64 r; asm("mov.b64 %0,{%1,%2};" : "=l"(r) : "f"(lo), "f"(hi)); return r;
}
__device__ __forceinline__ u64 dup2(float v) {
    u64 r; asm("mov.b64 %0,{%1,%1};" : "=l"(r) : "f"(v)); return r;
}
__device__ __forceinline__ void upk2(u64 p, float& lo, float& hi) {
    asm("mov.b64 {%0,%1},%2;" : "=f"(lo), "=f"(hi) : "l"(p));
}
__device__ __forceinline__ u64 ffma2(u64 a, u64 b, u64 c) {
    u64 d; asm("fma.rn.f32x2 %0,%1,%2,%3;" : "=l"(d) : "l"(a), "l"(b), "l"(c)); return d;
}
__device__ __forceinline__ u64 fadd2(u64 a, u64 b) {
    u64 d; asm("add.rn.f32x2 %0,%1,%2;" : "=l"(d) : "l"(a), "l"(b)); return d;
}
__device__ __forceinline__ u64 fsub2(u64 a, u64 b) {
    u64 d; asm("sub.rn.f32x2 %0,%1,%2;" : "=l"(d) : "l"(a), "l"(b)); return d;
}

// ---------------------------------------------------------------------------
// Kernel 1: cur1[t,b,h] = sum_f x[b,t,f] * W1[h,f] + b1[h]
// grid = (2, T). Tile BM=64(b) x BN=128(h), BK=32, 4x8 per thread, 256 thr.
// Math in packed fp32x2 (FFMA2): 2 IEEE fp32 FMAs per fma-pipe slot.
// Precision shield: fresh chunk accumulator per BK=32 slab, Kahan-merged
// (packed) into running accumulator -> dot error ~1e-7 std.
// ---------------------------------------------------------------------------
__global__ void __launch_bounds__(256, 2) gemm1_kernel(
    const float* __restrict__ x,   // [B, T, F]
    const float* __restrict__ W1,  // [H, F]
    const float* __restrict__ b1)  // [H]
{
    const int bm  = blockIdx.x;   // 0..1 (b tile)
    const int t   = blockIdx.y;   // 0..255
    const int tid = threadIdx.x;

    __shared__ float Xs[32][68];   // [k][b], +4 pad
    __shared__ float Ws[32][132];  // [k][h], +4 pad

    // Packed accumulators: [row i][col pair j] covers cols tc*8 + 2j, 2j+1
    u64 accP[4][4], compP[4][4], caccP[4][4];
    #pragma unroll
    for (int i = 0; i < 4; i++)
        #pragma unroll
        for (int j = 0; j < 4; j++) { accP[i][j] = 0ull; compP[i][j] = 0ull; }

    const int tr = tid >> 4;   // 0..15 -> b rows tr*4..+3
    const int tc = tid & 15;   // 0..15 -> h cols tc*8..+7

    for (int k0 = 0; k0 < F_SZ; k0 += 32) {
        // Load Xs: 64 rows x 32 k = 512 float4, 2 per thread.
        #pragma unroll
        for (int i = 0; i < 2; i++) {
            const int L  = tid + 256 * i;     // 0..511
            const int r  = L >> 3;            // 0..63
            const int kv = (L & 7) << 2;      // 0,4,...,28
            const int f  = k0 + kv;
            float4 v = make_float4(0.f, 0.f, 0.f, 0.f);
            if (f < F_SZ)  // F_SZ % 4 == 0 -> float4 fully valid or fully OOB
                v = *reinterpret_cast<const float4*>(
                        &x[((bm * 64 + r) * T_STEPS + t) * F_SZ + f]);
            Xs[kv + 0][r] = v.x; Xs[kv + 1][r] = v.y;
            Xs[kv + 2][r] = v.z; Xs[kv + 3][r] = v.w;
        }
        // Load Ws: 128 rows x 32 k = 1024 float4, 4 per thread.
        #pragma unroll
        for (int i = 0; i < 4; i++) {
            const int L  = tid + 256 * i;     // 0..1023
            const int r  = L >> 3;            // 0..127
            const int kv = (L & 7) << 2;
            const int f  = k0 + kv;
            float4 v = make_float4(0.f, 0.f, 0.f, 0.f);
            if (f < F_SZ)
                v = *reinterpret_cast<const float4*>(&W1[r * F_SZ + f]);
            Ws[kv + 0][r] = v.x; Ws[kv + 1][r] = v.y;
            Ws[kv + 2][r] = v.z; Ws[kv + 3][r] = v.w;
        }
        __syncthreads();

        #pragma unroll
        for (int i = 0; i < 4; i++)
            #pragma unroll
            for (int j = 0; j < 4; j++) caccP[i][j] = 0ull;

        #pragma unroll 8
        for (int k = 0; k < 32; k++) {
            float a[4], b[8];
            *reinterpret_cast<float4*>(a)     = *reinterpret_cast<const float4*>(&Xs[k][tr * 4]);
            *reinterpret_cast<float4*>(b)     = *reinterpret_cast<const float4*>(&Ws[k][tc * 8]);
            *reinterpret_cast<float4*>(b + 4) = *reinterpret_cast<const float4*>(&Ws[k][tc * 8 + 4]);
            u64 aP[4], bP[4];
            #pragma unroll
            for (int i = 0; i < 4; i++) aP[i] = dup2(a[i]);
            #pragma unroll
            for (int j = 0; j < 4; j++) bP[j] = pk2(b[2 * j], b[2 * j + 1]);
            #pragma unroll
            for (int i = 0; i < 4; i++)
                #pragma unroll
                for (int j = 0; j < 4; j++)
                    caccP[i][j] = ffma2(aP[i], bP[j], caccP[i][j]);
        }

        // Kahan merge (packed) of chunk sum into running accumulator
        #pragma unroll
        for (int i = 0; i < 4; i++)
            #pragma unroll
            for (int j = 0; j < 4; j++) {
                u64 y   = fsub2(caccP[i][j], compP[i][j]);
                u64 tmp = fadd2(accP[i][j], y);
                compP[i][j] = fsub2(fsub2(tmp, accP[i][j]), y);
                accP[i][j]  = tmp;
            }
        __syncthreads();
    }

    float bias[8];
    #pragma unroll
    for (int j = 0; j < 8; j++) bias[j] = b1[tc * 8 + j];

    #pragma unroll
    for (int i = 0; i < 4; i++) {
        const int brow = bm * 64 + tr * 4 + i;
        float* dst = &g_cur1[(t * B_SZ + brow) * H_SZ + tc * 8];
        float r[8];
        #pragma unroll
        for (int j = 0; j < 4; j++) {
            u64 v = fadd2(accP[i][j], compP[i][j]);
            float lo, hi; upk2(v, lo, hi);
            r[2 * j]     = lo + bias[2 * j];
            r[2 * j + 1] = hi + bias[2 * j + 1];
        }
        *reinterpret_cast<float4*>(dst)     = *reinterpret_cast<float4*>(r);
        *reinterpret_cast<float4*>(dst + 4) = *reinterpret_cast<float4*>(r + 4);
    }
}

// ---------------------------------------------------------------------------
// Kernel 2: LIF layer 1 in fp64. One thread per (b,h) = 16384 threads.
// ---------------------------------------------------------------------------
__global__ void lif1_kernel()
{
    const int g = blockIdx.x * blockDim.x + threadIdx.x;  // b*H + h
    const double beta = (double)0.9f;  // match reference's fp32 constant
    double mem = 0.0;
    for (int t0 = 0; t0 < T_STEPS; t0 += 8) {
        float c[8];
        #pragma unroll
        for (int i = 0; i < 8; i++)
            c[i] = g_cur1[(t0 + i) * (B_SZ * H_SZ) + g];
        #pragma unroll
        for (int i = 0; i < 8; i++) {
            const double rst = (mem > 1.0) ? 1.0 : 0.0;
            mem = beta * mem + (double)c[i] - rst;
            g_spk1[(t0 + i) * (B_SZ * H_SZ) + g] = (mem > 1.0) ? 1.0f : 0.0f;
        }
    }
}

// ---------------------------------------------------------------------------
// Kernel 3: cur2[t,b,o] = sum_h spk1[t,b,h] * W2[o,h] + b2[o]  (fp64 exact:
// spk1 in {0,1} so products are exact fp32, summed in double).
// One warp per (t,b): 32768 warps.
// ---------------------------------------------------------------------------
__global__ void cur2_kernel(const float* __restrict__ W2, const float* __restrict__ b2)
{
    const int gw   = (blockIdx.x * blockDim.x + threadIdx.x) >> 5;  // t*B + b
    const int lane = threadIdx.x & 31;
    const float* row = g_spk1 + (size_t)gw * H_SZ;

    double s0 = 0.0, s1 = 0.0;
    #pragma unroll
    for (int j = 0; j < 4; j++) {
        const int h = lane + j * 32;
        const float v = row[h];
        s0 += (double)(v * W2[h]);
        s1 += (double)(v * W2[H_SZ + h]);
    }
    #pragma unroll
    for (int off = 16; off > 0; off >>= 1) {
        s0 += __shfl_xor_sync(0xffffffffu, s0, off);
        s1 += __shfl_xor_sync(0xffffffffu, s1, off);
    }
    if (lane == 0) {
        g_cur2[gw * 2 + 0] = s0 + (double)b2[0];
        g_cur2[gw * 2 + 1] = s1 + (double)b2[1];
    }
}

// ---------------------------------------------------------------------------
// Kernel 4: LIF layer 2 in fp64 + write outputs.
// 8 blocks x 32 threads (one thread per (b,o) chain); chunk=8 so the staging
// array stays in registers (the old c[16] doubles spilled -> 79us).
// out = [spk_rec (T,B,O) | mem_rec (T,B,O)] flattened, fp32.
// ---------------------------------------------------------------------------
__global__ void lif2_kernel(float* __restrict__ out)
{
    const int g = blockIdx.x * blockDim.x + threadIdx.x;  // b*O + o, 0..255
    float* out_spk = out;
    float* out_mem = out + T_STEPS * B_SZ * O_SZ;
    const double beta = (double)0.9f;

    double mem = 0.0;
    for (int t0 = 0; t0 < T_STEPS; t0 += 8) {
        double c[8];
        #pragma unroll
        for (int i = 0; i < 8; i++)
            c[i] = g_cur2[(t0 + i) * (B_SZ * O_SZ) + g];
        #pragma unroll
        for (int i = 0; i < 8; i++) {
            const double rst = (mem > 1.0) ? 1.0 : 0.0;
            mem = beta * mem + c[i] - rst;
            out_spk[(t0 + i) * (B_SZ * O_SZ) + g] = (mem > 1.0) ? 1.0f : 0.0f;
            out_mem[(t0 + i) * (B_SZ * O_SZ) + g] = (float)mem;
        }
    }
}

// ---------------------------------------------------------------------------
extern "C" void kernel_launch(void* const* d_in, const int* in_sizes, int n_in,
                              void* d_out, int out_size)
{
    const float* x  = (const float*)d_in[0];  // [B, T, F]
    const float* W1 = (const float*)d_in[1];  // [H, F]
    const float* b1 = (const float*)d_in[2];  // [H]
    const float* W2 = (const float*)d_in[3];  // [O, H]
    const float* b2 = (const float*)d_in[4];  // [O]
    float* out = (float*)d_out;

    dim3 g1(2, T_STEPS);
    gemm1_kernel<<<g1, 256>>>(x, W1, b1);                      // 512 CTAs
    lif1_kernel<<<(B_SZ * H_SZ) / 256, 256>>>();               // 64 CTAs
    cur2_kernel<<<(T_STEPS * B_SZ * 32) / 256, 256>>>(W2, b2); // 4096 CTAs
    lif2_kernel<<<8, 32>>>(out);                               // tiny serial tail
}